// round 16
// baseline (speedup 1.0000x reference)
#include <cuda_runtime.h>
#include <cstdint>

// Fixed problem shape: N=50000, E=800000, F=64, IN=128
#define NN_MAX 50000
#define NE_MAX 800000
#define ET_MAX (NE_MAX + NN_MAX)
#define SCAN_B 1024
#define NBLK ((NN_MAX + SCAN_B - 1) / SCAN_B)   // 49

// ---------------- scratch (static device globals; no allocation) -------------
__device__ __align__(16) float g_xl[NN_MAX * 64];
__device__ __align__(16) float g_xr[NN_MAX * 64];
__device__ __align__(16) float g_h [NN_MAX * 64];
__device__ int   g_srcs[ET_MAX];
__device__ int   g_es[ET_MAX];
__device__ int   g_ed[ET_MAX];
__device__ int   g_cnt[NN_MAX];
__device__ int   g_row[NN_MAX];
__device__ int   g_cur[NN_MAX];
__device__ int   g_bsum[NBLK];

// ---------------- CSR build (unchanged) --------------------------------------
__global__ void zero_cnt(int n) {
    int i = blockIdx.x * blockDim.x + threadIdx.x;
    if (i < n) { g_cnt[i] = 0; g_cur[i] = 0; }
}

__global__ void prep_hist(const int* __restrict__ ei, int E, int n) {
    int i = blockIdx.x * blockDim.x + threadIdx.x;
    if (i < E) {
        int s = ei[i], d = ei[E + i];
        s = min(max(s, 0), n - 1);
        d = min(max(d, 0), n - 1);
        g_es[i] = s; g_ed[i] = d;
        atomicAdd(&g_cnt[d], 1);
    }
    if (i < n) {
        g_es[E + i] = i; g_ed[E + i] = i;
        atomicAdd(&g_cnt[i], 1);
    }
}

__global__ void scan1(int n) {
    __shared__ int sm[SCAN_B];
    int tid = threadIdx.x, i = blockIdx.x * SCAN_B + tid;
    int v = (i < n) ? g_cnt[i] : 0;
    sm[tid] = v; __syncthreads();
    for (int off = 1; off < SCAN_B; off <<= 1) {
        int t = (tid >= off) ? sm[tid - off] : 0;
        __syncthreads();
        sm[tid] += t; __syncthreads();
    }
    if (i < n) g_row[i] = sm[tid] - v;
    if (tid == SCAN_B - 1) g_bsum[blockIdx.x] = sm[tid];
}
__global__ void scan2() {
    if (threadIdx.x == 0) {
        int acc = 0;
        for (int b = 0; b < NBLK; b++) { int t = g_bsum[b]; g_bsum[b] = acc; acc += t; }
    }
}
__global__ void scan3(int n) {
    int i = blockIdx.x * blockDim.x + threadIdx.x;
    if (i < n) g_row[i] += g_bsum[i >> 10];
}

__global__ void scatter(int etot) {
    int i = blockIdx.x * blockDim.x + threadIdx.x;
    if (i < etot) {
        int d = g_ed[i];
        int pos = g_row[d] + atomicAdd(&g_cur[d], 1);
        g_srcs[pos] = g_es[i];
    }
}

// ---------------- TF32 helpers ------------------------------------------------
__device__ __forceinline__ float f2tf32(float x) {
    uint32_t r;
    asm("cvt.rna.tf32.f32 %0, %1;" : "=r"(r) : "f"(x));
    return __uint_as_float(r);
}

#define MMA_TF32(Cv, A0, A1, A2, A3, B0, B1)                                    \
    asm("mma.sync.aligned.m16n8k8.row.col.f32.tf32.tf32.f32 "                   \
        "{%0,%1,%2,%3},{%4,%5,%6,%7},{%8,%9},{%0,%1,%2,%3};"                    \
        : "+f"((Cv)[0]), "+f"((Cv)[1]), "+f"((Cv)[2]), "+f"((Cv)[3])            \
        : "r"(A0), "r"(A1), "r"(A2), "r"(A3), "r"(B0), "r"(B1))

// ---------------- dual GEMM v5: TF32 tensor-core, 3xTF32 compensated ---------
// Block 256 thr = 8 warps; tile M=128 rows x N=128 (Wl 64 | Wr 64).
// Warp w owns rows [16w,16w+16): 16 mma n-tiles. K chunks of 16 (2 mma-k).
// smem packs hi/lo + k/k+4 per float4 -> 1 LDS.128 per fragment element pair.
//   As4[s][tig][row] = {hi(X[row][8s+tig]), lo(..), hi(X[row][8s+tig+4]), lo(..)}
//   Bs4[s][tig][col] = {hi(W[8s+tig][col]), lo(..), hi(W[8s+tig+4][col]), lo(..)}
// D = Xhi*Whi + Xhi*Wlo + Xlo*Whi  (error ~2^-22; rel_err stays ~1e-7)
template <int K>
__global__ __launch_bounds__(256) void gemm_dual(const float* Xin,
                          const float* __restrict__ Wl,
                          const float* __restrict__ Wr,
                          int n) {
    const float* __restrict__ X = Xin ? Xin : g_h;
    __shared__ float4 As4[2][4][132];
    __shared__ float4 Bs4[2][4][132];
    const int t = threadIdx.x;
    const int row0 = blockIdx.x * 128;
    const int lane = t & 31, w = t >> 5;
    const int group = lane >> 2, tig = lane & 3;

    float C[16][4];
#pragma unroll
    for (int i = 0; i < 16; i++)
#pragma unroll
        for (int j = 0; j < 4; j++) C[i][j] = 0.0f;

    for (int k0 = 0; k0 < K; k0 += 16) {
        // ---- stage A: 128 rows x 16 ks. thread: row=t>>1, s=t&1 (8 ks) ----
        {
            int r = t >> 1;
            int s = t & 1;
            int gr = row0 + r;
            float4 v0, v1;
            if (gr < n) {
                v0 = *(const float4*)&X[gr * K + k0 + 8 * s];
                v1 = *(const float4*)&X[gr * K + k0 + 8 * s + 4];
            } else {
                v0 = make_float4(0.f, 0.f, 0.f, 0.f);
                v1 = v0;
            }
            float e[8] = {v0.x, v0.y, v0.z, v0.w, v1.x, v1.y, v1.z, v1.w};
#pragma unroll
            for (int j = 0; j < 8; j++) {
                float hi = f2tf32(e[j]);
                float lo = f2tf32(e[j] - hi);
                int tg = j & 3, half = j >> 2;      // k = tg (+4 if half)
                float* dst = (float*)&As4[s][tg][r];
                dst[half * 2]     = hi;
                dst[half * 2 + 1] = lo;
            }
        }
        // ---- stage B: 16 ks x 128 cols. thread: kk=t>>4, cols=(t&15)*8 ----
        {
            int kk = t >> 4;
            int c0 = (t & 15) * 8;
            const float* Wm = (c0 < 64) ? &Wl[(k0 + kk) * 64 + c0]
                                        : &Wr[(k0 + kk) * 64 + (c0 - 64)];
            float4 v0 = *(const float4*)&Wm[0];
            float4 v1 = *(const float4*)&Wm[4];
            float e[8] = {v0.x, v0.y, v0.z, v0.w, v1.x, v1.y, v1.z, v1.w};
            int s = kk >> 3, kpos = kk & 7;
            int tg = kpos & 3, half = kpos >> 2;
#pragma unroll
            for (int j = 0; j < 8; j++) {
                float hi = f2tf32(e[j]);
                float lo = f2tf32(e[j] - hi);
                float* dst = (float*)&Bs4[s][tg][c0 + j];
                dst[half * 2]     = hi;
                dst[half * 2 + 1] = lo;
            }
        }
        __syncthreads();

#pragma unroll
        for (int s = 0; s < 2; s++) {
            float4 A0 = As4[s][tig][w * 16 + group];
            float4 A1 = As4[s][tig][w * 16 + group + 8];
            uint32_t a0h = __float_as_uint(A0.x), a0l = __float_as_uint(A0.y);
            uint32_t a2h = __float_as_uint(A0.z), a2l = __float_as_uint(A0.w);
            uint32_t a1h = __float_as_uint(A1.x), a1l = __float_as_uint(A1.y);
            uint32_t a3h = __float_as_uint(A1.z), a3l = __float_as_uint(A1.w);
#pragma unroll
            for (int nt = 0; nt < 16; nt++) {
                float4 B = Bs4[s][tig][nt * 8 + group];
                uint32_t b0h = __float_as_uint(B.x), b0l = __float_as_uint(B.y);
                uint32_t b1h = __float_as_uint(B.z), b1l = __float_as_uint(B.w);
                MMA_TF32(C[nt], a0h, a1h, a2h, a3h, b0h, b1h);
                MMA_TF32(C[nt], a0h, a1h, a2h, a3h, b0l, b1l);
                MMA_TF32(C[nt], a0l, a1l, a2l, a3l, b0h, b1h);
            }
        }
        __syncthreads();
    }

    // ---- epilogue ----
    int rA = row0 + w * 16 + group;
    int rB = rA + 8;
#pragma unroll
    for (int nt = 0; nt < 16; nt++) {
        float* O = (nt < 8) ? g_xl : g_xr;
        int col = (nt & 7) * 8 + tig * 2;
        if (rA < n) *(float2*)&O[rA * 64 + col] = make_float2(C[nt][0], C[nt][1]);
        if (rB < n) *(float2*)&O[rB * 64 + col] = make_float2(C[nt][2], C[nt][3]);
    }
}

// ---------------- single-pass fused GATv2 node kernel (unchanged) ------------
__device__ __forceinline__ float dot_leaky(float4 a, float4 xr, float4 av) {
    float ux = a.x + xr.x; ux = (ux > 0.0f) ? ux : 0.2f * ux;
    float uy = a.y + xr.y; uy = (uy > 0.0f) ? uy : 0.2f * uy;
    float uz = a.z + xr.z; uz = (uz > 0.0f) ? uz : 0.2f * uz;
    float uw = a.w + xr.w; uw = (uw > 0.0f) ? uw : 0.2f * uw;
    return fmaf(ux, av.x, fmaf(uy, av.y, fmaf(uz, av.z, uw * av.w)));
}

__global__ __launch_bounds__(256) void node_fused(const float* __restrict__ att,
                           const float* __restrict__ bias,
                           float* outp, int do_relu, int n) {
    float* __restrict__ out = outp ? outp : g_h;
    int node = (blockIdx.x * blockDim.x + threadIdx.x) >> 5;
    if (node >= n) return;
    const int lane = threadIdx.x & 31;
    const int half = lane >> 4;
    const int hl   = lane & 15;

    const int beg = g_row[node];
    const int deg = g_cnt[node];
    const int end = beg + deg;

    const float4 xr4 = *(const float4*)&g_xr[node * 64 + hl * 4];
    const float4 av4 = *(const float4*)&att[hl * 4];

    float ssum = 0.0f;
    float4 acc = make_float4(0.0f, 0.0f, 0.0f, 0.0f);

    for (int kk = 0; kk < deg; kk += 4) {
        int i0 = beg + kk + half;
        int i1 = beg + kk + 2 + half;
        bool v0 = i0 < end, v1 = i1 < end;
        int s0 = g_srcs[v0 ? i0 : beg];
        int s1 = g_srcs[v1 ? i1 : beg];
        float4 a0 = *(const float4*)&g_xl[s0 * 64 + hl * 4];
        float4 a1 = *(const float4*)&g_xl[s1 * 64 + hl * 4];

        float p0 = dot_leaky(a0, xr4, av4);
        float p1 = dot_leaky(a1, xr4, av4);
#pragma unroll
        for (int o = 1; o < 16; o <<= 1) {
            p0 += __shfl_xor_sync(0xffffffffu, p0, o);
            p1 += __shfl_xor_sync(0xffffffffu, p1, o);
        }
        float e0 = v0 ? __expf(p0) : 0.0f;
        float e1 = v1 ? __expf(p1) : 0.0f;
        ssum += e0 + e1;
        acc.x = fmaf(e0, a0.x, fmaf(e1, a1.x, acc.x));
        acc.y = fmaf(e0, a0.y, fmaf(e1, a1.y, acc.y));
        acc.z = fmaf(e0, a0.z, fmaf(e1, a1.z, acc.z));
        acc.w = fmaf(e0, a0.w, fmaf(e1, a1.w, acc.w));
    }

    ssum  += __shfl_xor_sync(0xffffffffu, ssum, 16);
    acc.x += __shfl_xor_sync(0xffffffffu, acc.x, 16);
    acc.y += __shfl_xor_sync(0xffffffffu, acc.y, 16);
    acc.z += __shfl_xor_sync(0xffffffffu, acc.z, 16);
    acc.w += __shfl_xor_sync(0xffffffffu, acc.w, 16);

    const float inv = 1.0f / (ssum + 1e-16f);
    float4 b4 = *(const float4*)&bias[hl * 4];
    float4 r;
    r.x = fmaf(acc.x, inv, b4.x);
    r.y = fmaf(acc.y, inv, b4.y);
    r.z = fmaf(acc.z, inv, b4.z);
    r.w = fmaf(acc.w, inv, b4.w);
    if (do_relu) {
        r.x = fmaxf(r.x, 0.0f); r.y = fmaxf(r.y, 0.0f);
        r.z = fmaxf(r.z, 0.0f); r.w = fmaxf(r.w, 0.0f);
    }
    if (half == 0) *(float4*)&out[node * 64 + hl * 4] = r;
}

// ---------------- launch ------------------------------------------------------
extern "C" void kernel_launch(void* const* d_in, const int* in_sizes, int n_in,
                              void* d_out, int out_size) {
    const float* x    = (const float*)d_in[0];
    const int*   ei   = (const int*)d_in[1];    // int32 (JAX x64 disabled)
    const float* W1l  = (const float*)d_in[2];
    const float* W1r  = (const float*)d_in[3];
    const float* att1 = (const float*)d_in[4];
    const float* b1   = (const float*)d_in[5];
    const float* W2l  = (const float*)d_in[6];
    const float* W2r  = (const float*)d_in[7];
    const float* att2 = (const float*)d_in[8];
    const float* b2   = (const float*)d_in[9];

    const int n    = in_sizes[0] / 128;   // 50000
    const int E    = in_sizes[1] / 2;     // 800000
    const int etot = E + n;

    float* out = (float*)d_out;
    const int B = 256;

    zero_cnt<<<(n + B - 1) / B, B>>>(n);
    prep_hist<<<(E + B - 1) / B, B>>>(ei, E, n);
    scan1<<<NBLK, SCAN_B>>>(n);
    gemm_dual<128><<<(n + 127) / 128, 256>>>(x, W1l, W1r, n);   // 4th: profiled
    scan2<<<1, 32>>>();
    scan3<<<(n + B - 1) / B, B>>>(n);
    scatter<<<(etot + B - 1) / B, B>>>(etot);

    const int gridNode = (n * 32 + B - 1) / B;

    // ---- layer 1 aggregation ----
    node_fused<<<gridNode, B>>>(att1, b1, nullptr, 1, n);

    // ---- layer 2 ----
    gemm_dual<64><<<(n + 127) / 128, 256>>>(nullptr, W2l, W2r, n);
    node_fused<<<gridNode, B>>>(att2, b2, out, 0, n);
}

// round 17
// speedup vs baseline: 1.2245x; 1.2245x over previous
#include <cuda_runtime.h>
#include <cstdint>

// Fixed problem shape: N=50000, E=800000, F=64, IN=128
#define NN_MAX 50000
#define NE_MAX 800000
#define ET_MAX (NE_MAX + NN_MAX)
#define SCAN_B 1024
#define NBLK ((NN_MAX + SCAN_B - 1) / SCAN_B)   // 49

// ---------------- scratch (static device globals; no allocation) -------------
__device__ __align__(16) float g_xl[NN_MAX * 64];
__device__ __align__(16) float g_xr[NN_MAX * 64];
__device__ __align__(16) float g_h [NN_MAX * 64];
__device__ int   g_srcs[ET_MAX];
__device__ int   g_es[ET_MAX];
__device__ int   g_ed[ET_MAX];
__device__ int   g_cnt[NN_MAX];
__device__ int   g_row[NN_MAX];
__device__ int   g_cur[NN_MAX];
__device__ int   g_bsum[NBLK];

// ---------------- CSR build (unchanged) --------------------------------------
__global__ void zero_cnt(int n) {
    int i = blockIdx.x * blockDim.x + threadIdx.x;
    if (i < n) { g_cnt[i] = 0; g_cur[i] = 0; }
}

__global__ void prep_hist(const int* __restrict__ ei, int E, int n) {
    int i = blockIdx.x * blockDim.x + threadIdx.x;
    if (i < E) {
        int s = ei[i], d = ei[E + i];
        s = min(max(s, 0), n - 1);
        d = min(max(d, 0), n - 1);
        g_es[i] = s; g_ed[i] = d;
        atomicAdd(&g_cnt[d], 1);
    }
    if (i < n) {
        g_es[E + i] = i; g_ed[E + i] = i;
        atomicAdd(&g_cnt[i], 1);
    }
}

__global__ void scan1(int n) {
    __shared__ int sm[SCAN_B];
    int tid = threadIdx.x, i = blockIdx.x * SCAN_B + tid;
    int v = (i < n) ? g_cnt[i] : 0;
    sm[tid] = v; __syncthreads();
    for (int off = 1; off < SCAN_B; off <<= 1) {
        int t = (tid >= off) ? sm[tid - off] : 0;
        __syncthreads();
        sm[tid] += t; __syncthreads();
    }
    if (i < n) g_row[i] = sm[tid] - v;
    if (tid == SCAN_B - 1) g_bsum[blockIdx.x] = sm[tid];
}
__global__ void scan2() {
    if (threadIdx.x == 0) {
        int acc = 0;
        for (int b = 0; b < NBLK; b++) { int t = g_bsum[b]; g_bsum[b] = acc; acc += t; }
    }
}
__global__ void scan3(int n) {
    int i = blockIdx.x * blockDim.x + threadIdx.x;
    if (i < n) g_row[i] += g_bsum[i >> 10];
}

__global__ void scatter(int etot) {
    int i = blockIdx.x * blockDim.x + threadIdx.x;
    if (i < etot) {
        int d = g_ed[i];
        int pos = g_row[d] + atomicAdd(&g_cur[d], 1);
        g_srcs[pos] = g_es[i];
    }
}

// ---------------- TF32 helpers ------------------------------------------------
__device__ __forceinline__ float f2tf32(float x) {
    uint32_t r;
    asm("cvt.rna.tf32.f32 %0, %1;" : "=r"(r) : "f"(x));
    return __uint_as_float(r);
}

#define MMA_TF32(Cv, A0, A1, A2, A3, B0, B1)                                    \
    asm("mma.sync.aligned.m16n8k8.row.col.f32.tf32.tf32.f32 "                   \
        "{%0,%1,%2,%3},{%4,%5,%6,%7},{%8,%9},{%0,%1,%2,%3};"                    \
        : "+f"((Cv)[0]), "+f"((Cv)[1]), "+f"((Cv)[2]), "+f"((Cv)[3])            \
        : "r"(A0), "r"(A1), "r"(A2), "r"(A3), "r"(B0), "r"(B1))

// ---------------- dual GEMM v6: TF32 MMA, conflict-free smem -----------------
// Same math/fragment mapping as v5 (PASSED, rel_err 1.4e-6) but:
//  * plane stride 130 float4 -> plane bank bases {0,8,16,24}: fragment
//    LDS.128 hits all 32 banks/phase (4 WF, optimal; was 8).
//  * staging via STS.64 {hi,lo} with conflict-free thread mappings.
// Pack slot: P4[(s*4+tg)*130 + idx] = {hi(k=8s+tg), lo, hi(k=8s+tg+4), lo}.
template <int K>
__global__ __launch_bounds__(256) void gemm_dual(const float* Xin,
                          const float* __restrict__ Wl,
                          const float* __restrict__ Wr,
                          int n) {
    const float* __restrict__ X = Xin ? Xin : g_h;
    __shared__ float4 As4[8 * 130];
    __shared__ float4 Bs4[8 * 130];
    const int t = threadIdx.x;
    const int row0 = blockIdx.x * 128;
    const int lane = t & 31, w = t >> 5;
    const int group = lane >> 2, tig = lane & 3;

    float C[16][4];
#pragma unroll
    for (int i = 0; i < 16; i++)
#pragma unroll
        for (int j = 0; j < 4; j++) C[i][j] = 0.0f;

    for (int k0 = 0; k0 < K; k0 += 16) {
        // ---- stage A: tasks = 128 rows x 4 quarters. r=idx>>2, q=idx&3.
        // LDG: lanes 0-3 cover 64B of one row (8 rows/warp -> 8 lines).
        // STS.64: phase lanes (r0..7, same q-set per j) -> banks 4r distinct.
#pragma unroll
        for (int i = 0; i < 2; i++) {
            int idx = t + i * 256;
            int r = idx >> 2, q = idx & 3;
            int s = q >> 1, half = q & 1;
            int gr = row0 + r;
            float4 v = (gr < n) ? *(const float4*)&X[gr * K + k0 + 4 * q]
                                : make_float4(0.f, 0.f, 0.f, 0.f);
            float e[4] = {v.x, v.y, v.z, v.w};
#pragma unroll
            for (int j = 0; j < 4; j++) {
                float hi = f2tf32(e[j]);
                float lo = f2tf32(e[j] - hi);
                float* dst = (float*)&As4[(s * 4 + j) * 130 + r] + half * 2;
                *(float2*)dst = make_float2(hi, lo);
            }
        }
        // ---- stage B: tasks = 16 ks x 32 col-groups. kk=idx&15, cg=idx>>4.
        // W is L1-resident (reused by all blocks); STS.64 conflict-free:
        // banks 8tg+2half+4j distinct across phase.
#pragma unroll
        for (int i = 0; i < 2; i++) {
            int idx = t + i * 256;
            int kk = idx & 15, cg = idx >> 4;
            int c0 = cg * 4;
            int s = kk >> 3, krel = kk & 7;
            int tg = krel & 3, half = krel >> 2;
            const float* Wm = (c0 < 64) ? &Wl[(k0 + kk) * 64 + c0]
                                        : &Wr[(k0 + kk) * 64 + (c0 - 64)];
            float4 v = *(const float4*)Wm;
            float e[4] = {v.x, v.y, v.z, v.w};
#pragma unroll
            for (int j = 0; j < 4; j++) {
                float hi = f2tf32(e[j]);
                float lo = f2tf32(e[j] - hi);
                float* dst = (float*)&Bs4[(s * 4 + tg) * 130 + c0 + j] + half * 2;
                *(float2*)dst = make_float2(hi, lo);
            }
        }
        __syncthreads();

#pragma unroll
        for (int s = 0; s < 2; s++) {
            float4 A0 = As4[(s * 4 + tig) * 130 + w * 16 + group];
            float4 A1 = As4[(s * 4 + tig) * 130 + w * 16 + group + 8];
            uint32_t a0h = __float_as_uint(A0.x), a0l = __float_as_uint(A0.y);
            uint32_t a2h = __float_as_uint(A0.z), a2l = __float_as_uint(A0.w);
            uint32_t a1h = __float_as_uint(A1.x), a1l = __float_as_uint(A1.y);
            uint32_t a3h = __float_as_uint(A1.z), a3l = __float_as_uint(A1.w);
#pragma unroll
            for (int nt = 0; nt < 16; nt++) {
                float4 B = Bs4[(s * 4 + tig) * 130 + nt * 8 + group];
                uint32_t b0h = __float_as_uint(B.x), b0l = __float_as_uint(B.y);
                uint32_t b1h = __float_as_uint(B.z), b1l = __float_as_uint(B.w);
                MMA_TF32(C[nt], a0h, a1h, a2h, a3h, b0h, b1h);
                MMA_TF32(C[nt], a0h, a1h, a2h, a3h, b0l, b1l);
                MMA_TF32(C[nt], a0l, a1l, a2l, a3l, b0h, b1h);
            }
        }
        __syncthreads();
    }

    // ---- epilogue (unchanged from v5) ----
    int rA = row0 + w * 16 + group;
    int rB = rA + 8;
#pragma unroll
    for (int nt = 0; nt < 16; nt++) {
        float* O = (nt < 8) ? g_xl : g_xr;
        int col = (nt & 7) * 8 + tig * 2;
        if (rA < n) *(float2*)&O[rA * 64 + col] = make_float2(C[nt][0], C[nt][1]);
        if (rB < n) *(float2*)&O[rB * 64 + col] = make_float2(C[nt][2], C[nt][3]);
    }
}

// ---------------- single-pass fused GATv2 node kernel (unchanged) ------------
__device__ __forceinline__ float dot_leaky(float4 a, float4 xr, float4 av) {
    float ux = a.x + xr.x; ux = (ux > 0.0f) ? ux : 0.2f * ux;
    float uy = a.y + xr.y; uy = (uy > 0.0f) ? uy : 0.2f * uy;
    float uz = a.z + xr.z; uz = (uz > 0.0f) ? uz : 0.2f * uz;
    float uw = a.w + xr.w; uw = (uw > 0.0f) ? uw : 0.2f * uw;
    return fmaf(ux, av.x, fmaf(uy, av.y, fmaf(uz, av.z, uw * av.w)));
}

__global__ __launch_bounds__(256) void node_fused(const float* __restrict__ att,
                           const float* __restrict__ bias,
                           float* outp, int do_relu, int n) {
    float* __restrict__ out = outp ? outp : g_h;
    int node = (blockIdx.x * blockDim.x + threadIdx.x) >> 5;
    if (node >= n) return;
    const int lane = threadIdx.x & 31;
    const int half = lane >> 4;
    const int hl   = lane & 15;

    const int beg = g_row[node];
    const int deg = g_cnt[node];
    const int end = beg + deg;

    const float4 xr4 = *(const float4*)&g_xr[node * 64 + hl * 4];
    const float4 av4 = *(const float4*)&att[hl * 4];

    float ssum = 0.0f;
    float4 acc = make_float4(0.0f, 0.0f, 0.0f, 0.0f);

    for (int kk = 0; kk < deg; kk += 4) {
        int i0 = beg + kk + half;
        int i1 = beg + kk + 2 + half;
        bool v0 = i0 < end, v1 = i1 < end;
        int s0 = g_srcs[v0 ? i0 : beg];
        int s1 = g_srcs[v1 ? i1 : beg];
        float4 a0 = *(const float4*)&g_xl[s0 * 64 + hl * 4];
        float4 a1 = *(const float4*)&g_xl[s1 * 64 + hl * 4];

        float p0 = dot_leaky(a0, xr4, av4);
        float p1 = dot_leaky(a1, xr4, av4);
#pragma unroll
        for (int o = 1; o < 16; o <<= 1) {
            p0 += __shfl_xor_sync(0xffffffffu, p0, o);
            p1 += __shfl_xor_sync(0xffffffffu, p1, o);
        }
        float e0 = v0 ? __expf(p0) : 0.0f;
        float e1 = v1 ? __expf(p1) : 0.0f;
        ssum += e0 + e1;
        acc.x = fmaf(e0, a0.x, fmaf(e1, a1.x, acc.x));
        acc.y = fmaf(e0, a0.y, fmaf(e1, a1.y, acc.y));
        acc.z = fmaf(e0, a0.z, fmaf(e1, a1.z, acc.z));
        acc.w = fmaf(e0, a0.w, fmaf(e1, a1.w, acc.w));
    }

    ssum  += __shfl_xor_sync(0xffffffffu, ssum, 16);
    acc.x += __shfl_xor_sync(0xffffffffu, acc.x, 16);
    acc.y += __shfl_xor_sync(0xffffffffu, acc.y, 16);
    acc.z += __shfl_xor_sync(0xffffffffu, acc.z, 16);
    acc.w += __shfl_xor_sync(0xffffffffu, acc.w, 16);

    const float inv = 1.0f / (ssum + 1e-16f);
    float4 b4 = *(const float4*)&bias[hl * 4];
    float4 r;
    r.x = fmaf(acc.x, inv, b4.x);
    r.y = fmaf(acc.y, inv, b4.y);
    r.z = fmaf(acc.z, inv, b4.z);
    r.w = fmaf(acc.w, inv, b4.w);
    if (do_relu) {
        r.x = fmaxf(r.x, 0.0f); r.y = fmaxf(r.y, 0.0f);
        r.z = fmaxf(r.z, 0.0f); r.w = fmaxf(r.w, 0.0f);
    }
    if (half == 0) *(float4*)&out[node * 64 + hl * 4] = r;
}

// ---------------- launch ------------------------------------------------------
extern "C" void kernel_launch(void* const* d_in, const int* in_sizes, int n_in,
                              void* d_out, int out_size) {
    const float* x    = (const float*)d_in[0];
    const int*   ei   = (const int*)d_in[1];    // int32 (JAX x64 disabled)
    const float* W1l  = (const float*)d_in[2];
    const float* W1r  = (const float*)d_in[3];
    const float* att1 = (const float*)d_in[4];
    const float* b1   = (const float*)d_in[5];
    const float* W2l  = (const float*)d_in[6];
    const float* W2r  = (const float*)d_in[7];
    const float* att2 = (const float*)d_in[8];
    const float* b2   = (const float*)d_in[9];

    const int n    = in_sizes[0] / 128;   // 50000
    const int E    = in_sizes[1] / 2;     // 800000
    const int etot = E + n;

    float* out = (float*)d_out;
    const int B = 256;

    zero_cnt<<<(n + B - 1) / B, B>>>(n);
    prep_hist<<<(E + B - 1) / B, B>>>(ei, E, n);
    scan1<<<NBLK, SCAN_B>>>(n);
    gemm_dual<128><<<(n + 127) / 128, 256>>>(x, W1l, W1r, n);   // 4th: profiled
    scan2<<<1, 32>>>();
    scan3<<<(n + B - 1) / B, B>>>(n);
    scatter<<<(etot + B - 1) / B, B>>>(etot);

    const int gridNode = (n * 32 + B - 1) / B;

    // ---- layer 1 aggregation ----
    node_fused<<<gridNode, B>>>(att1, b1, nullptr, 1, n);

    // ---- layer 2 ----
    gemm_dual<64><<<(n + 127) / 128, 256>>>(nullptr, W2l, W2r, n);
    node_fused<<<gridNode, B>>>(att2, b2, out, 0, n);
}